// round 12
// baseline (speedup 1.0000x reference)
#include <cuda_runtime.h>
#include <cuda_fp16.h>
#include <cstdint>

#define BTOT  16384
#define T     28
#define INP   28
#define H     64
#define MROWS 128
#define NT    512
#define OUTD  10

// ---- dynamic SMEM layout (byte offsets) ----
// A tiles fp16, double-buffered: [rf 0..7][kf 0..5][lane 0..31][16B]
#define ABUF    24576
#define OFF_A0  0
#define OFF_A1  24576
// B tile fp16: [wn 0..7][kf 0..5][nf 0..3][lane 0..31][8B]
#define OFF_B   49152
// dedicated f32 h_last dump
#define OFF_HF  98304
#define SMEM_BYTES (98304 + 32768)
// epilogue reuse (A1/B dead after the loop)
#define OFF_WFC  36864
#define OFF_BFC  39424
#define OFF_PART 40960

__device__ __forceinline__ uint32_t smem_u32(const void* p) {
    uint32_t a;
    asm("{ .reg .u64 t; cvta.to.shared.u64 t, %1; cvt.u32.u64 %0, t; }" : "=r"(a) : "l"(p));
    return a;
}
__device__ __forceinline__ void sts32(uint32_t a, uint32_t v) {
    asm volatile("st.shared.b32 [%0], %1;" :: "r"(a), "r"(v) : "memory");
}
__device__ __forceinline__ void lds128(uint32_t* r, uint32_t a) {
    asm volatile("ld.shared.v4.b32 {%0,%1,%2,%3}, [%4];"
                 : "=r"(r[0]), "=r"(r[1]), "=r"(r[2]), "=r"(r[3]) : "r"(a));
}
__device__ __forceinline__ void lds64(uint32_t* r, uint32_t a) {
    asm volatile("ld.shared.v2.b32 {%0,%1}, [%2];" : "=r"(r[0]), "=r"(r[1]) : "r"(a));
}
// group barrier: 256 threads (8 warps) of group id-1
#define BARG(id) asm volatile("bar.sync %0, %1;" :: "r"(id), "r"(256) : "memory")

// pack two f32 into f16x2 (round-to-nearest)
__device__ __forceinline__ uint32_t pack2h(float a, float b) {
    __half2 h2 = __floats2half2_rn(a, b);
    return *reinterpret_cast<uint32_t*>(&h2);
}

// dual-state activations on the MUFU pipe (1 op per 2 states)
__device__ __forceinline__ __half2 tanh2h(__half2 v) {
    uint32_t y, xx = *reinterpret_cast<uint32_t*>(&v);
    asm("tanh.approx.f16x2 %0, %1;" : "=r"(y) : "r"(xx));
    return *reinterpret_cast<__half2*>(&y);
}
__device__ __forceinline__ __half2 tanh2f(float a, float b) {
    return tanh2h(__floats2half2_rn(a, b));
}
__device__ __forceinline__ __half2 sigm2(float a, float b) {
    const __half2 h5 = __float2half2_rn(0.5f);
    return __hfma2(tanh2h(__floats2half2_rn(0.5f * a, 0.5f * b)), h5, h5);
}

// m16n8k16 fp16 MMA, D += A*B (C aliased to D), f32 accumulate
__device__ __forceinline__ void mma16816(float* d, const uint32_t* a, const uint32_t* b) {
    asm volatile(
        "mma.sync.aligned.m16n8k16.row.col.f32.f16.f16.f32 "
        "{%0,%1,%2,%3}, {%4,%5,%6,%7}, {%8,%9}, {%0,%1,%2,%3};"
        : "+f"(d[0]), "+f"(d[1]), "+f"(d[2]), "+f"(d[3])
        : "r"(a[0]), "r"(a[1]), "r"(a[2]), "r"(a[3]), "r"(b[0]), "r"(b[1]));
}

// weight element with K mapping: k 0..27 -> W_ih, 28..31 -> 0, 32..95 -> W_hh
__device__ __forceinline__ float wval(const float* __restrict__ Wih,
                                      const float* __restrict__ Whh, int g, int k) {
    if (k < INP)  return Wih[g * INP + k];
    if (k < 32)   return 0.0f;
    return Whh[g * H + (k - 32)];
}

__global__ void __launch_bounds__(NT, 1) lstm_mma_kernel(
    const float* __restrict__ x,    const float* __restrict__ W_ih,
    const float* __restrict__ W_hh, const float* __restrict__ b_ih,
    const float* __restrict__ b_hh, const float* __restrict__ W_fc,
    const float* __restrict__ b_fc, float* __restrict__ out)
{
    extern __shared__ char sm[];
    const uint32_t sb  = smem_u32(sm);
    const int tid  = threadIdx.x;
    const int w5   = tid >> 5;          // warp 0..15
    const int wn   = w5 >> 1;           // unit-group: owns units wn*8..wn*8+7
    const int grp  = w5 & 1;            // row-half group: rows grp*64..grp*64+63
    const int lane = tid & 31;
    const int g8   = lane >> 2;         // groupID
    const int tig  = lane & 3;          // threadID in group
    const int b0   = blockIdx.x * MROWS;
    const int tg   = wn * 32 + lane;    // 0..255 index within my group

    // ---- zero both A buffers (covers x-pad k28..31 and h0 = 0) ----
    {
        uint4* az = reinterpret_cast<uint4*>(sm);
        uint4 z = make_uint4(0u, 0u, 0u, 0u);
        for (int i = tid; i < OFF_B / 16; i += NT) az[i] = z;
    }

    // ---- build B fragments (fp16), fragment-major ----
    for (int ii = tid; ii < 8 * 6 * 4 * 32 * 2; ii += NT) {
        int reg = ii & 1;
        int t_  = (ii >> 1) & 31;
        int nf  = (ii >> 6) & 3;
        int kfn = (ii >> 8);
        int kf  = kfn % 6;
        int w_  = kfn / 6;
        int k0  = kf * 16 + reg * 8 + 2 * (t_ & 3);
        int g   = nf * 64 + w_ * 8 + (t_ >> 2);
        float v0 = wval(W_ih, W_hh, g, k0);
        float v1 = wval(W_ih, W_hh, g, k0 + 1);
        uint32_t boff = (uint32_t)(((w_ * 6 + kf) * 4 + nf) * 256 + t_ * 8 + reg * 4);
        sts32(sb + OFF_B + boff, pack2h(v0, v1));
    }

    // ---- per-thread bias ----
    float bias2[4][2];
#pragma unroll
    for (int nf = 0; nf < 4; nf++)
#pragma unroll
        for (int ul = 0; ul < 2; ul++) {
            int g = nf * 64 + wn * 8 + 2 * tig + ul;
            bias2[nf][ul] = b_ih[g] + b_hh[g];
        }

    // ---- x staging map (group-local): 64 rows x 14 pairs = 896 pairs/group ----
    int      xgb[4];
    uint32_t xsa[4];
    const int nxp = (tg < 896 - 3 * 256) ? 4 : 3;
#pragma unroll
    for (int i = 0; i < 4; i++) {
        int p  = tg + i * 256;
        if (p >= 896) p = 0;            // dummy (masked by nxp)
        int r  = grp * 64 + p / 14;
        int kp = (p % 14) * 2;
        xgb[i] = ((b0 + r) * T) * INP + kp;
        int rf = r >> 4, gp = r & 7, rh = (r >> 3) & 1;
        int kf = kp >> 4, ki = kp & 15;
        xsa[i] = (uint32_t)((rf * 6 + kf) * 512 + (gp * 4 + ((ki & 7) >> 1)) * 16
                            + (ki >> 3) * 8 + rh * 4);
    }

    __syncthreads();   // zeroing complete before x(0) staging

    // ---- stage x(0) into buffer 0 ----
#pragma unroll
    for (int i = 0; i < 4; i++) {
        if (i < nxp) {
            float2 v = *reinterpret_cast<const float2*>(x + xgb[i]);
            sts32(sb + OFF_A0 + xsa[i], pack2h(v.x, v.y));
        }
    }
    __syncthreads();   // full sync once; groups run on named barriers after this

    // ---- h writeback base (k0h = 32 + wn*8 + 2*tig), buffer-relative ----
    const int k0h = 32 + wn * 8 + 2 * tig;
    const uint32_t hbase = (uint32_t)(((k0h >> 4) * 32 + g8 * 4 + ((k0h & 7) >> 1)) * 16
                                      + ((k0h >> 3) & 1) * 8);
    const int bar = grp + 1;

    float c[16];
#pragma unroll
    for (int i = 0; i < 16; i++) c[i] = 0.0f;

    // =========================== timestep loop ===============================
    for (int t = 0; t < T; t++) {
        BARG(bar);     // my group's half of buf(t&1) staged (h + x from t-1)

        const uint32_t aCUR = sb + ((t & 1) ? OFF_A1 : OFF_A0);
        const uint32_t aNXT = sb + ((t & 1) ? OFF_A0 : OFF_A1);
        const bool last = (t == T - 1);

        // ---- D init = bias ----
        float d[4][4][4];
#pragma unroll
        for (int rf4 = 0; rf4 < 4; rf4++)
#pragma unroll
            for (int nf = 0; nf < 4; nf++)
#pragma unroll
                for (int sl = 0; sl < 4; sl++)
                    d[rf4][nf][sl] = bias2[nf][sl & 1];

        // ---- MMA phase: single term, 4 rf of my group's half ----
#pragma unroll
        for (int kf = 0; kf < 6; kf++) {
            uint32_t bh[4][2];
#pragma unroll
            for (int nf = 0; nf < 4; nf++) {
                uint32_t boff = (uint32_t)(((wn * 6 + kf) * 4 + nf) * 256 + lane * 8);
                lds64(bh[nf], sb + OFF_B + boff);
            }
#pragma unroll
            for (int rf4 = 0; rf4 < 4; rf4++) {
                const int rf = grp * 4 + rf4;
                uint32_t aoff = (uint32_t)((rf * 6 + kf) * 512 + lane * 16);
                uint32_t ah[4];
                lds128(ah, aCUR + aoff);
#pragma unroll
                for (int nf = 0; nf < 4; nf++)
                    mma16816(d[rf4][nf], ah, bh[nf]);
            }
        }

        // ---- prefetch x(t+1) ----
        float2 xp[4];
        if (!last) {
#pragma unroll
            for (int i = 0; i < 4; i++)
                if (i < nxp)
                    xp[i] = *reinterpret_cast<const float2*>(x + xgb[i] + (t + 1) * INP);
        }

        // ---- eltwise: dual-state f16x2 activations (5 MUFU per 2 states) ----
#pragma unroll
        for (int rf4 = 0; rf4 < 4; rf4++) {
            const int rf = grp * 4 + rf4;
#pragma unroll
            for (int rh = 0; rh < 2; rh++) {
                const int s0 = 2 * rh;
                const int ci = rf4 * 4 + s0;
                float2 gi = __half22float2(sigm2(d[rf4][0][s0], d[rf4][0][s0 + 1]));
                float2 gf = __half22float2(sigm2(d[rf4][1][s0], d[rf4][1][s0 + 1]));
                float2 gg = __half22float2(tanh2f(d[rf4][2][s0], d[rf4][2][s0 + 1]));
                __half2 go2 = sigm2(d[rf4][3][s0], d[rf4][3][s0 + 1]);
                float cm0 = fmaf(gf.x, c[ci],     gi.x * gg.x);
                float cm1 = fmaf(gf.y, c[ci + 1], gi.y * gg.y);
                c[ci] = cm0; c[ci + 1] = cm1;
                __half2 h2 = __hmul2(go2, tanh2f(cm0, cm1));   // h pair, fp16
                if (!last) {
                    uint32_t a = (uint32_t)(rf * 3072) + hbase + (uint32_t)(rh * 4);
                    sts32(aNXT + a, *reinterpret_cast<uint32_t*>(&h2));
                } else {
                    int r  = rf * 16 + g8 + 8 * rh;
                    int j0 = wn * 8 + 2 * tig;
                    float2 hf2 = __half22float2(h2);
                    float* hf = reinterpret_cast<float*>(sm + OFF_HF);
                    hf[r * H + j0]     = hf2.x;
                    hf[r * H + j0 + 1] = hf2.y;
                }
            }
        }

        // ---- commit x(t+1) into the next buffer ----
        if (!last) {
#pragma unroll
            for (int i = 0; i < 4; i++)
                if (i < nxp)
                    sts32(aNXT + xsa[i], pack2h(xp[i].x, xp[i].y));
        }
    }

    // ======================= FC epilogue (fp32 SIMT, 4-way K split) ==========
    __syncthreads();   // both groups done; h_last complete
    float* smf = reinterpret_cast<float*>(sm);
    const float* hf = reinterpret_cast<const float*>(sm + OFF_HF);
    for (int i = tid; i < OUTD * H; i += NT) smf[OFF_WFC / 4 + i] = W_fc[i];
    if (tid < OUTD) smf[OFF_BFC / 4 + tid] = b_fc[tid];
    __syncthreads();
    {
        const int q = tid >> 7, rr = tid & 127;   // quarter q sums k in [q*16, q*16+16)
        float acc[OUTD];
#pragma unroll
        for (int o = 0; o < OUTD; o++) acc[o] = 0.0f;
#pragma unroll
        for (int p = 0; p < 16; p++) {
            int k = q * 16 + p;
            float hvv = hf[rr * H + k];
#pragma unroll
            for (int o = 0; o < OUTD; o++)
                acc[o] = fmaf(hvv, smf[OFF_WFC / 4 + o * H + k], acc[o]);
        }
#pragma unroll
        for (int o = 0; o < OUTD; o++)
            smf[OFF_PART / 4 + (q * 128 + rr) * OUTD + o] = acc[o];
    }
    __syncthreads();
    for (int i = tid; i < MROWS * OUTD; i += NT) {
        int rr = i / OUTD, o = i - rr * OUTD;
        out[(size_t)(b0 + rr) * OUTD + o] =
            smf[OFF_PART / 4 + rr * OUTD + o]
          + smf[OFF_PART / 4 + (128 + rr) * OUTD + o]
          + smf[OFF_PART / 4 + (256 + rr) * OUTD + o]
          + smf[OFF_PART / 4 + (384 + rr) * OUTD + o]
          + smf[OFF_BFC / 4 + o];
    }
}

extern "C" void kernel_launch(void* const* d_in, const int* in_sizes, int n_in,
                              void* d_out, int out_size) {
    const float* x    = (const float*)d_in[0];
    const float* W_ih = (const float*)d_in[1];
    const float* W_hh = (const float*)d_in[2];
    const float* b_ih = (const float*)d_in[3];
    const float* b_hh = (const float*)d_in[4];
    const float* W_fc = (const float*)d_in[5];
    const float* b_fc = (const float*)d_in[6];

    cudaFuncSetAttribute(lstm_mma_kernel,
                         cudaFuncAttributeMaxDynamicSharedMemorySize, SMEM_BYTES);
    lstm_mma_kernel<<<BTOT / MROWS, NT, SMEM_BYTES>>>(
        x, W_ih, W_hh, b_ih, b_hh, W_fc, b_fc, (float*)d_out);
}

// round 13
// speedup vs baseline: 1.1508x; 1.1508x over previous
#include <cuda_runtime.h>
#include <cuda_fp16.h>
#include <cstdint>

#define BTOT  16384
#define T     28
#define INP   28
#define H     64
#define MROWS 64
#define NT    256
#define OUTD  10

// ---- dynamic SMEM layout (byte offsets) ----
// A tiles fp16, double-buffered: [rf 0..3][kf 0..5][lane 0..31][16B] = 12KB each
#define OFF_A0  0
#define OFF_A1  12288
// B tile fp16: [wn 0..7][kf 0..5][nf 0..3][lane 0..31][8B] = 48KB
#define OFF_B   24576
// dedicated f32 h_last dump: 64 x 64 f32 = 16KB
#define OFF_HF  73728
#define SMEM_BYTES (73728 + 16384)
// epilogue scratch reuses dead B region
#define OFF_WFC  24576
#define OFF_BFC  27136
#define OFF_PART 27264      // 4 * 64 * 10 f32 = 10240 B

__device__ __forceinline__ uint32_t smem_u32(const void* p) {
    uint32_t a;
    asm("{ .reg .u64 t; cvta.to.shared.u64 t, %1; cvt.u32.u64 %0, t; }" : "=r"(a) : "l"(p));
    return a;
}
__device__ __forceinline__ void sts32(uint32_t a, uint32_t v) {
    asm volatile("st.shared.b32 [%0], %1;" :: "r"(a), "r"(v) : "memory");
}
__device__ __forceinline__ void lds128(uint32_t* r, uint32_t a) {
    asm volatile("ld.shared.v4.b32 {%0,%1,%2,%3}, [%4];"
                 : "=r"(r[0]), "=r"(r[1]), "=r"(r[2]), "=r"(r[3]) : "r"(a));
}
__device__ __forceinline__ void lds64(uint32_t* r, uint32_t a) {
    asm volatile("ld.shared.v2.b32 {%0,%1}, [%2];" : "=r"(r[0]), "=r"(r[1]) : "r"(a));
}

// pack two f32 into f16x2 (round-to-nearest)
__device__ __forceinline__ uint32_t pack2h(float a, float b) {
    __half2 h2 = __floats2half2_rn(a, b);
    return *reinterpret_cast<uint32_t*>(&h2);
}

// f32 MUFU tanh (value paths: g gate, tanh(c))
__device__ __forceinline__ float tanha(float x) {
    float y; asm("tanh.approx.f32 %0, %1;" : "=f"(y) : "f"(x)); return y;
}
// dual-state fp16 sigmoid (multiplier gates only)
__device__ __forceinline__ __half2 tanh2h(__half2 v) {
    uint32_t y, xx = *reinterpret_cast<uint32_t*>(&v);
    asm("tanh.approx.f16x2 %0, %1;" : "=r"(y) : "r"(xx));
    return *reinterpret_cast<__half2*>(&y);
}
__device__ __forceinline__ float2 sigm2(float a, float b) {
    const __half2 h5 = __float2half2_rn(0.5f);
    __half2 s = __hfma2(tanh2h(__floats2half2_rn(0.5f * a, 0.5f * b)), h5, h5);
    return __half22float2(s);
}

// m16n8k16 fp16 MMA, D += A*B (C aliased to D), f32 accumulate
__device__ __forceinline__ void mma16816(float* d, const uint32_t* a, const uint32_t* b) {
    asm volatile(
        "mma.sync.aligned.m16n8k16.row.col.f32.f16.f16.f32 "
        "{%0,%1,%2,%3}, {%4,%5,%6,%7}, {%8,%9}, {%0,%1,%2,%3};"
        : "+f"(d[0]), "+f"(d[1]), "+f"(d[2]), "+f"(d[3])
        : "r"(a[0]), "r"(a[1]), "r"(a[2]), "r"(a[3]), "r"(b[0]), "r"(b[1]));
}

// weight element with K mapping: k 0..27 -> W_ih, 28..31 -> 0, 32..95 -> W_hh
__device__ __forceinline__ float wval(const float* __restrict__ Wih,
                                      const float* __restrict__ Whh, int g, int k) {
    if (k < INP)  return Wih[g * INP + k];
    if (k < 32)   return 0.0f;
    return Whh[g * H + (k - 32)];
}

__global__ void __launch_bounds__(NT, 2) lstm_mma_kernel(
    const float* __restrict__ x,    const float* __restrict__ W_ih,
    const float* __restrict__ W_hh, const float* __restrict__ b_ih,
    const float* __restrict__ b_hh, const float* __restrict__ W_fc,
    const float* __restrict__ b_fc, float* __restrict__ out)
{
    extern __shared__ char sm[];
    const uint32_t sb  = smem_u32(sm);
    const int tid  = threadIdx.x;
    const int wn   = tid >> 5;          // warp 0..7: owns units wn*8..wn*8+7
    const int lane = tid & 31;
    const int g8   = lane >> 2;         // groupID
    const int tig  = lane & 3;          // threadID in group
    const int b0   = blockIdx.x * MROWS;

    // ---- zero both A buffers (covers x-pad k28..31 and h0 = 0) ----
    {
        uint4* az = reinterpret_cast<uint4*>(sm);
        uint4 z = make_uint4(0u, 0u, 0u, 0u);
        for (int i = tid; i < OFF_B / 16; i += NT) az[i] = z;
    }

    // ---- build B fragments (fp16), fragment-major ----
    for (int ii = tid; ii < 8 * 6 * 4 * 32 * 2; ii += NT) {
        int reg = ii & 1;
        int t_  = (ii >> 1) & 31;
        int nf  = (ii >> 6) & 3;
        int kfn = (ii >> 8);
        int kf  = kfn % 6;
        int w_  = kfn / 6;
        int k0  = kf * 16 + reg * 8 + 2 * (t_ & 3);
        int g   = nf * 64 + w_ * 8 + (t_ >> 2);
        float v0 = wval(W_ih, W_hh, g, k0);
        float v1 = wval(W_ih, W_hh, g, k0 + 1);
        uint32_t boff = (uint32_t)(((w_ * 6 + kf) * 4 + nf) * 256 + t_ * 8 + reg * 4);
        sts32(sb + OFF_B + boff, pack2h(v0, v1));
    }

    // ---- per-thread bias ----
    float bias2[4][2];
#pragma unroll
    for (int nf = 0; nf < 4; nf++)
#pragma unroll
        for (int ul = 0; ul < 2; ul++) {
            int g = nf * 64 + wn * 8 + 2 * tig + ul;
            bias2[nf][ul] = b_ih[g] + b_hh[g];
        }

    // ---- x staging map: 64 rows x 14 pairs = 896 pairs, up to 4/thread ----
    int      xgb[4];
    uint32_t xsa[4];
    const int nxp = (tid < 896 - 3 * NT) ? 4 : 3;
#pragma unroll
    for (int i = 0; i < 4; i++) {
        int p  = tid + i * NT;
        if (p >= 896) p = 0;            // dummy (masked by nxp)
        int r  = p / 14;
        int kp = (p % 14) * 2;
        xgb[i] = ((b0 + r) * T) * INP + kp;
        int rf = r >> 4, gp = r & 7, rh = (r >> 3) & 1;
        int kf = kp >> 4, ki = kp & 15;
        xsa[i] = (uint32_t)((rf * 6 + kf) * 512 + (gp * 4 + ((ki & 7) >> 1)) * 16
                            + (ki >> 3) * 8 + rh * 4);
    }

    __syncthreads();   // zeroing complete before x(0) staging

    // ---- stage x(0) into buffer 0 ----
#pragma unroll
    for (int i = 0; i < 4; i++) {
        if (i < nxp) {
            float2 v = *reinterpret_cast<const float2*>(x + xgb[i]);
            sts32(sb + OFF_A0 + xsa[i], pack2h(v.x, v.y));
        }
    }

    // ---- h writeback base (k0h = 32 + wn*8 + 2*tig), buffer-relative ----
    const int k0h = 32 + wn * 8 + 2 * tig;
    const uint32_t hbase = (uint32_t)(((k0h >> 4) * 32 + g8 * 4 + ((k0h & 7) >> 1)) * 16
                                      + ((k0h >> 3) & 1) * 8);

    float c[16];
#pragma unroll
    for (int i = 0; i < 16; i++) c[i] = 0.0f;

    // =========================== timestep loop ===============================
    for (int t = 0; t < T; t++) {
        __syncthreads();   // buf(t&1) fully staged (h + x from t-1)

        const uint32_t aCUR = sb + ((t & 1) ? OFF_A1 : OFF_A0);
        const uint32_t aNXT = sb + ((t & 1) ? OFF_A0 : OFF_A1);
        const bool last = (t == T - 1);

        // ---- D init = bias ----
        float d[4][4][4];
#pragma unroll
        for (int rf = 0; rf < 4; rf++)
#pragma unroll
            for (int nf = 0; nf < 4; nf++)
#pragma unroll
                for (int sl = 0; sl < 4; sl++)
                    d[rf][nf][sl] = bias2[nf][sl & 1];

        // ---- MMA phase: single term, all 4 rf ----
#pragma unroll
        for (int kf = 0; kf < 6; kf++) {
            uint32_t bh[4][2];
#pragma unroll
            for (int nf = 0; nf < 4; nf++) {
                uint32_t boff = (uint32_t)(((wn * 6 + kf) * 4 + nf) * 256 + lane * 8);
                lds64(bh[nf], sb + OFF_B + boff);
            }
#pragma unroll
            for (int rf = 0; rf < 4; rf++) {
                uint32_t aoff = (uint32_t)((rf * 6 + kf) * 512 + lane * 16);
                uint32_t ah[4];
                lds128(ah, aCUR + aoff);
#pragma unroll
                for (int nf = 0; nf < 4; nf++)
                    mma16816(d[rf][nf], ah, bh[nf]);
            }
        }

        // ---- prefetch x(t+1) ----
        float2 xp[4];
        if (!last) {
#pragma unroll
            for (int i = 0; i < 4; i++)
                if (i < nxp)
                    xp[i] = *reinterpret_cast<const float2*>(x + xgb[i] + (t + 1) * INP);
        }

        // ---- eltwise: fp16 sigmoids (multipliers), f32 tanh (value paths) ----
#pragma unroll
        for (int rf = 0; rf < 4; rf++) {
#pragma unroll
            for (int rh = 0; rh < 2; rh++) {
                const int s0 = 2 * rh;
                const int ci = rf * 4 + s0;
                float2 gi = sigm2(d[rf][0][s0], d[rf][0][s0 + 1]);
                float2 gf = sigm2(d[rf][1][s0], d[rf][1][s0 + 1]);
                float2 go = sigm2(d[rf][3][s0], d[rf][3][s0 + 1]);
                float gg0 = tanha(d[rf][2][s0]);
                float gg1 = tanha(d[rf][2][s0 + 1]);
                float cm0 = fmaf(gf.x, c[ci],     gi.x * gg0);
                float cm1 = fmaf(gf.y, c[ci + 1], gi.y * gg1);
                c[ci] = cm0; c[ci + 1] = cm1;
                float hv0 = go.x * tanha(cm0);
                float hv1 = go.y * tanha(cm1);
                if (!last) {
                    uint32_t a = (uint32_t)(rf * 3072) + hbase + (uint32_t)(rh * 4);
                    sts32(aNXT + a, pack2h(hv0, hv1));
                } else {
                    int r  = rf * 16 + g8 + 8 * rh;
                    int j0 = wn * 8 + 2 * tig;
                    float* hf = reinterpret_cast<float*>(sm + OFF_HF);
                    hf[r * H + j0]     = hv0;
                    hf[r * H + j0 + 1] = hv1;
                }
            }
        }

        // ---- commit x(t+1) into the next buffer ----
        if (!last) {
#pragma unroll
            for (int i = 0; i < 4; i++)
                if (i < nxp)
                    sts32(aNXT + xsa[i], pack2h(xp[i].x, xp[i].y));
        }
    }

    // ======================= FC epilogue (fp32 SIMT, 4-way K split) ==========
    __syncthreads();   // h_last complete
    float* smf = reinterpret_cast<float*>(sm);
    const float* hf = reinterpret_cast<const float*>(sm + OFF_HF);
    for (int i = tid; i < OUTD * H; i += NT) smf[OFF_WFC / 4 + i] = W_fc[i];
    if (tid < OUTD) smf[OFF_BFC / 4 + tid] = b_fc[tid];
    __syncthreads();
    {
        const int q = tid >> 6, rr = tid & 63;   // quarter q sums k in [q*16, q*16+16)
        float acc[OUTD];
#pragma unroll
        for (int o = 0; o < OUTD; o++) acc[o] = 0.0f;
#pragma unroll
        for (int p = 0; p < 16; p++) {
            int k = q * 16 + p;
            float hvv = hf[rr * H + k];
#pragma unroll
            for (int o = 0; o < OUTD; o++)
                acc[o] = fmaf(hvv, smf[OFF_WFC / 4 + o * H + k], acc[o]);
        }
#pragma unroll
        for (int o = 0; o < OUTD; o++)
            smf[OFF_PART / 4 + (q * 64 + rr) * OUTD + o] = acc[o];
    }
    __syncthreads();
    for (int i = tid; i < MROWS * OUTD; i += NT) {
        int rr = i / OUTD, o = i - rr * OUTD;
        out[(size_t)(b0 + rr) * OUTD + o] =
            smf[OFF_PART / 4 + rr * OUTD + o]
          + smf[OFF_PART / 4 + (64 + rr) * OUTD + o]
          + smf[OFF_PART / 4 + (128 + rr) * OUTD + o]
          + smf[OFF_PART / 4 + (192 + rr) * OUTD + o]
          + smf[OFF_BFC / 4 + o];
    }
}

extern "C" void kernel_launch(void* const* d_in, const int* in_sizes, int n_in,
                              void* d_out, int out_size) {
    const float* x    = (const float*)d_in[0];
    const float* W_ih = (const float*)d_in[1];
    const float* W_hh = (const float*)d_in[2];
    const float* b_ih = (const float*)d_in[3];
    const float* b_hh = (const float*)d_in[4];
    const float* W_fc = (const float*)d_in[5];
    const float* b_fc = (const float*)d_in[6];

    cudaFuncSetAttribute(lstm_mma_kernel,
                         cudaFuncAttributeMaxDynamicSharedMemorySize, SMEM_BYTES);
    lstm_mma_kernel<<<BTOT / MROWS, NT, SMEM_BYTES>>>(
        x, W_ih, W_hh, b_ih, b_hh, W_fc, b_fc, (float*)d_out);
}

// round 14
// speedup vs baseline: 1.1761x; 1.0220x over previous
#include <cuda_runtime.h>
#include <cuda_fp16.h>
#include <cstdint>

#define BTOT  16384
#define T     28
#define INP   28
#define H     64
#define MROWS 64
#define NT    256
#define OUTD  10

// ---- dynamic SMEM layout (byte offsets) ----
// A tiles fp16, double-buffered: [rfA 0..3][kf 0..5][lane 0..31][16B] = 12KB each
#define OFF_A0   0
#define OFF_A1   12288
// B tile fp16: [wq 0..3][kf 0..5][nf 0..7][lane 0..31][8B] = 48KB
#define OFF_B    24576
// bias f32[256]
#define OFF_BIAS 73728
// dedicated f32 h_last dump: 64 x 64 f32 = 16KB
#define OFF_HF   74752
#define SMEM_BYTES (74752 + 16384)
// epilogue scratch reuses dead B region
#define OFF_WFC  24576
#define OFF_BFC  27136
#define OFF_PART 27264

__device__ __forceinline__ uint32_t smem_u32(const void* p) {
    uint32_t a;
    asm("{ .reg .u64 t; cvta.to.shared.u64 t, %1; cvt.u32.u64 %0, t; }" : "=r"(a) : "l"(p));
    return a;
}
__device__ __forceinline__ void sts32(uint32_t a, uint32_t v) {
    asm volatile("st.shared.b32 [%0], %1;" :: "r"(a), "r"(v) : "memory");
}
__device__ __forceinline__ void lds128(uint32_t* r, uint32_t a) {
    asm volatile("ld.shared.v4.b32 {%0,%1,%2,%3}, [%4];"
                 : "=r"(r[0]), "=r"(r[1]), "=r"(r[2]), "=r"(r[3]) : "r"(a));
}
__device__ __forceinline__ void lds64(uint32_t* r, uint32_t a) {
    asm volatile("ld.shared.v2.b32 {%0,%1}, [%2];" : "=r"(r[0]), "=r"(r[1]) : "r"(a));
}
__device__ __forceinline__ float2 lds64f(uint32_t a) {
    float2 v;
    asm volatile("ld.shared.v2.f32 {%0,%1}, [%2];" : "=f"(v.x), "=f"(v.y) : "r"(a));
    return v;
}
// group barrier: 128 threads (4 warps, one per SMSP) of group id-1
#define BARG(id) asm volatile("bar.sync %0, %1;" :: "r"(id), "r"(128) : "memory")

// pack two f32 into f16x2 (round-to-nearest)
__device__ __forceinline__ uint32_t pack2h(float a, float b) {
    __half2 h2 = __floats2half2_rn(a, b);
    return *reinterpret_cast<uint32_t*>(&h2);
}

// f32 MUFU tanh (value paths: g gate, tanh(c))
__device__ __forceinline__ float tanha(float x) {
    float y; asm("tanh.approx.f32 %0, %1;" : "=f"(y) : "f"(x)); return y;
}
// dual-state fp16 sigmoid (multiplier gates only)
__device__ __forceinline__ __half2 tanh2h(__half2 v) {
    uint32_t y, xx = *reinterpret_cast<uint32_t*>(&v);
    asm("tanh.approx.f16x2 %0, %1;" : "=r"(y) : "r"(xx));
    return *reinterpret_cast<__half2*>(&y);
}
__device__ __forceinline__ float2 sigm2(float a, float b) {
    const __half2 h5 = __float2half2_rn(0.5f);
    __half2 s = __hfma2(tanh2h(__floats2half2_rn(0.5f * a, 0.5f * b)), h5, h5);
    return __half22float2(s);
}

// m16n8k16 fp16 MMA, D += A*B (C aliased to D), f32 accumulate
__device__ __forceinline__ void mma16816(float* d, const uint32_t* a, const uint32_t* b) {
    asm volatile(
        "mma.sync.aligned.m16n8k16.row.col.f32.f16.f16.f32 "
        "{%0,%1,%2,%3}, {%4,%5,%6,%7}, {%8,%9}, {%0,%1,%2,%3};"
        : "+f"(d[0]), "+f"(d[1]), "+f"(d[2]), "+f"(d[3])
        : "r"(a[0]), "r"(a[1]), "r"(a[2]), "r"(a[3]), "r"(b[0]), "r"(b[1]));
}

// weight element with K mapping: k 0..27 -> W_ih, 28..31 -> 0, 32..95 -> W_hh
__device__ __forceinline__ float wval(const float* __restrict__ Wih,
                                      const float* __restrict__ Whh, int g, int k) {
    if (k < INP)  return Wih[g * INP + k];
    if (k < 32)   return 0.0f;
    return Whh[g * H + (k - 32)];
}

__global__ void __launch_bounds__(NT, 2) lstm_mma_kernel(
    const float* __restrict__ x,    const float* __restrict__ W_ih,
    const float* __restrict__ W_hh, const float* __restrict__ b_ih,
    const float* __restrict__ b_hh, const float* __restrict__ W_fc,
    const float* __restrict__ b_fc, float* __restrict__ out)
{
    extern __shared__ char sm[];
    const uint32_t sb  = smem_u32(sm);
    const int tid  = threadIdx.x;
    const int wid  = tid >> 5;
    const int grp  = wid >> 2;          // row group: rows grp*32..grp*32+31
    const int wq   = wid & 3;           // warp-in-group: one per SMSP; units wq*16..+15
    const int lane = tid & 31;
    const int g8   = lane >> 2;
    const int tig  = lane & 3;
    const int tg   = tid & 127;         // thread index within group
    const int b0   = blockIdx.x * MROWS;

    // ---- zero both A buffers (covers x-pad k28..31 and h0 = 0) ----
    {
        uint4* az = reinterpret_cast<uint4*>(sm);
        uint4 z = make_uint4(0u, 0u, 0u, 0u);
        for (int i = tid; i < OFF_B / 16; i += NT) az[i] = z;
    }

    // ---- build B fragments (fp16), fragment-major; nf = 2*gate + unit-half ----
    for (int ii = tid; ii < 4 * 6 * 8 * 32 * 2; ii += NT) {
        int reg  = ii & 1;
        int t_   = (ii >> 1) & 31;
        int nf   = (ii >> 6) & 7;
        int rest = ii >> 9;
        int kf   = rest % 6;
        int w_   = rest / 6;            // 0..3
        int k0   = kf * 16 + reg * 8 + 2 * (t_ & 3);
        int g    = (nf >> 1) * 64 + w_ * 16 + (nf & 1) * 8 + (t_ >> 2);
        float v0 = wval(W_ih, W_hh, g, k0);
        float v1 = wval(W_ih, W_hh, g, k0 + 1);
        uint32_t boff = (uint32_t)(((w_ * 6 + kf) * 8 + nf) * 256 + t_ * 8 + reg * 4);
        sts32(sb + OFF_B + boff, pack2h(v0, v1));
    }

    // ---- bias into smem (f32, gate-major) ----
    for (int g = tid; g < 256; g += NT)
        sts32(sb + OFF_BIAS + 4 * g, __float_as_uint(b_ih[g] + b_hh[g]));

    // ---- x staging map (group-local): 32 rows x 14 pairs = 448 pairs/group ----
    int      xgb[4];
    uint32_t xsa[4];
    const int nxp = (tg < 448 - 3 * 128) ? 4 : 3;
#pragma unroll
    for (int i = 0; i < 4; i++) {
        int p  = tg + i * 128;
        if (p >= 448) p = 0;            // dummy (masked by nxp)
        int r  = grp * 32 + p / 14;
        int kp = (p % 14) * 2;
        xgb[i] = ((b0 + r) * T) * INP + kp;
        int rfA = r >> 4, gp = r & 7, rhA = (r >> 3) & 1;
        int kf = kp >> 4, ki = kp & 15;
        xsa[i] = (uint32_t)((rfA * 6 + kf) * 512 + (gp * 4 + ((ki & 7) >> 1)) * 16
                            + (ki >> 3) * 8 + rhA * 4);
    }

    __syncthreads();   // zeroing complete before x(0) staging

    // ---- stage x(0) into buffer 0 ----
#pragma unroll
    for (int i = 0; i < 4; i++) {
        if (i < nxp) {
            float2 v = *reinterpret_cast<const float2*>(x + xgb[i]);
            sts32(sb + OFF_A0 + xsa[i], pack2h(v.x, v.y));
        }
    }
    __syncthreads();   // full sync once; groups run on named barriers after this

    const int bar = grp + 1;
    // bias base for this thread's units (per uh: +8 units = +32 bytes)
    const uint32_t biasb = sb + OFF_BIAS + (uint32_t)(wq * 16 + 2 * tig) * 4;

    float c[16];
#pragma unroll
    for (int i = 0; i < 16; i++) c[i] = 0.0f;

    // =========================== timestep loop ===============================
    for (int t = 0; t < T; t++) {
        BARG(bar);     // my group's rows of buf(t&1) staged (h + x from t-1)

        const uint32_t aCUR = sb + ((t & 1) ? OFF_A1 : OFF_A0);
        const uint32_t aNXT = sb + ((t & 1) ? OFF_A0 : OFF_A1);
        const bool last = (t == T - 1);

        // ---- D init = bias (from smem; nf = 2*gt + uh -> unit base uh*8) ----
        float d[2][8][4];
#pragma unroll
        for (int nf = 0; nf < 8; nf++) {
            float2 b2 = lds64f(biasb + (uint32_t)((nf >> 1) * 64 + (nf & 1) * 8) * 4);
#pragma unroll
            for (int rf = 0; rf < 2; rf++) {
                d[rf][nf][0] = b2.x; d[rf][nf][1] = b2.y;
                d[rf][nf][2] = b2.x; d[rf][nf][3] = b2.y;
            }
        }

        // ---- MMA phase: 2 rf x 6 kf x 8 nf ----
#pragma unroll
        for (int kf = 0; kf < 6; kf++) {
            uint32_t bh[8][2];
#pragma unroll
            for (int nf = 0; nf < 8; nf++) {
                uint32_t boff = (uint32_t)(((wq * 6 + kf) * 8 + nf) * 256 + lane * 8);
                lds64(bh[nf], sb + OFF_B + boff);
            }
#pragma unroll
            for (int rf = 0; rf < 2; rf++) {
                uint32_t aoff = (uint32_t)((((grp * 2 + rf) * 6 + kf) * 512) + lane * 16);
                uint32_t ah[4];
                lds128(ah, aCUR + aoff);
#pragma unroll
                for (int nf = 0; nf < 8; nf++)
                    mma16816(d[rf][nf], ah, bh[nf]);
            }
        }

        // ---- prefetch x(t+1) ----
        float2 xp[4];
        if (!last) {
#pragma unroll
            for (int i = 0; i < 4; i++)
                if (i < nxp)
                    xp[i] = *reinterpret_cast<const float2*>(x + xgb[i] + (t + 1) * INP);
        }

        // ---- eltwise: fp16 sigmoids (multipliers), f32 tanh (value paths) ----
#pragma unroll
        for (int rf = 0; rf < 2; rf++) {
#pragma unroll
            for (int rh = 0; rh < 2; rh++) {
#pragma unroll
                for (int uh = 0; uh < 2; uh++) {
                    const int s0 = 2 * rh;
                    const int ci = ((rf * 2 + rh) * 2 + uh) * 2;
                    float2 gi = sigm2(d[rf][0 + uh][s0], d[rf][0 + uh][s0 + 1]);
                    float2 gf = sigm2(d[rf][2 + uh][s0], d[rf][2 + uh][s0 + 1]);
                    float2 go = sigm2(d[rf][6 + uh][s0], d[rf][6 + uh][s0 + 1]);
                    float gg0 = tanha(d[rf][4 + uh][s0]);
                    float gg1 = tanha(d[rf][4 + uh][s0 + 1]);
                    float cm0 = fmaf(gf.x, c[ci],     gi.x * gg0);
                    float cm1 = fmaf(gf.y, c[ci + 1], gi.y * gg1);
                    c[ci] = cm0; c[ci + 1] = cm1;
                    float hv0 = go.x * tanha(cm0);
                    float hv1 = go.y * tanha(cm1);
                    if (!last) {
                        // k0 = 32 + wq*16 + uh*8 + 2*tig -> kf = 2+wq, ki = uh*8+2*tig
                        uint32_t a = (uint32_t)((((grp * 2 + rf) * 6 + 2 + wq) * 512)
                                     + (g8 * 4 + tig) * 16 + uh * 8 + rh * 4);
                        sts32(aNXT + a, pack2h(hv0, hv1));
                    } else {
                        int r  = grp * 32 + rf * 16 + rh * 8 + g8;
                        int j0 = wq * 16 + uh * 8 + 2 * tig;
                        float* hf = reinterpret_cast<float*>(sm + OFF_HF);
                        hf[r * H + j0]     = hv0;
                        hf[r * H + j0 + 1] = hv1;
                    }
                }
            }
        }

        // ---- commit x(t+1) into the next buffer ----
        if (!last) {
#pragma unroll
            for (int i = 0; i < 4; i++)
                if (i < nxp)
                    sts32(aNXT + xsa[i], pack2h(xp[i].x, xp[i].y));
        }
    }

    // ======================= FC epilogue (fp32 SIMT, 4-way K split) ==========
    __syncthreads();   // both groups done; h_last complete
    float* smf = reinterpret_cast<float*>(sm);
    const float* hf = reinterpret_cast<const float*>(sm + OFF_HF);
    for (int i = tid; i < OUTD * H; i += NT) smf[OFF_WFC / 4 + i] = W_fc[i];
    if (tid < OUTD) smf[OFF_BFC / 4 + tid] = b_fc[tid];
    __syncthreads();
    {
        const int q = tid >> 6, rr = tid & 63;   // quarter q sums k in [q*16, q*16+16)
        float acc[OUTD];
#pragma unroll
        for (int o = 0; o < OUTD; o++) acc[o] = 0.0f;
#pragma unroll
        for (int p = 0; p < 16; p++) {
            int k = q * 16 + p;
            float hvv = hf[rr * H + k];
#pragma unroll
            for (int o = 0; o < OUTD; o++)
                acc[o] = fmaf(hvv, smf[OFF_WFC / 4 + o * H + k], acc[o]);
        }
#pragma unroll
        for (int o = 0; o < OUTD; o++)
            smf[OFF_PART / 4 + (q * 64 + rr) * OUTD + o] = acc[o];
    }
    __syncthreads();
    for (int i = tid; i < MROWS * OUTD; i += NT) {
        int rr = i / OUTD, o = i - rr * OUTD;
        out[(size_t)(b0 + rr) * OUTD + o] =
            smf[OFF_PART / 4 + rr * OUTD + o]
          + smf[OFF_PART / 4 + (64 + rr) * OUTD + o]
          + smf[OFF_PART / 4 + (128 + rr) * OUTD + o]
          + smf[OFF_PART / 4 + (192 + rr) * OUTD + o]
          + smf[OFF_BFC / 4 + o];
    }
}

extern "C" void kernel_launch(void* const* d_in, const int* in_sizes, int n_in,
                              void* d_out, int out_size) {
    const float* x    = (const float*)d_in[0];
    const float* W_ih = (const float*)d_in[1];
    const float* W_hh = (const float*)d_in[2];
    const float* b_ih = (const float*)d_in[3];
    const float* b_hh = (const float*)d_in[4];
    const float* W_fc = (const float*)d_in[5];
    const float* b_fc = (const float*)d_in[6];

    cudaFuncSetAttribute(lstm_mma_kernel,
                         cudaFuncAttributeMaxDynamicSharedMemorySize, SMEM_BYTES);
    lstm_mma_kernel<<<BTOT / MROWS, NT, SMEM_BYTES>>>(
        x, W_ih, W_hh, b_ih, b_hh, W_fc, b_fc, (float*)d_out);
}

// round 16
// speedup vs baseline: 1.2578x; 1.0694x over previous
#include <cuda_runtime.h>
#include <cuda_fp16.h>
#include <cstdint>

#define BTOT  16384
#define T     28
#define INP   28
#define H     64
#define MROWS 128
#define NT    256
#define OUTD  10

// ---- dynamic SMEM layout (byte offsets) ----
// B tile fp16: [kf 0..5][nf 0..31][lane 0..31][8B] = 49152
#define OFF_B    0
#define OFF_BIAS 49152              // 256 f32
#define OFF_HF   50176              // h_last f32: 128 x 64 x 4 = 32768
#define SMEM_BYTES (50176 + 32768)
// epilogue scratch reuses dead B region
#define OFF_WFC  0                  // 10*64 f32 = 2560
#define OFF_BFC  2560               // 10 f32
#define OFF_PART 4096               // 2*128*10 f32 = 10240 (ends 14336 < 49152)

__device__ __forceinline__ uint32_t smem_u32(const void* p) {
    uint32_t a;
    asm("{ .reg .u64 t; cvta.to.shared.u64 t, %1; cvt.u32.u64 %0, t; }" : "=r"(a) : "l"(p));
    return a;
}
__device__ __forceinline__ void sts32(uint32_t a, uint32_t v) {
    asm volatile("st.shared.b32 [%0], %1;" :: "r"(a), "r"(v) : "memory");
}
__device__ __forceinline__ void lds64(uint32_t* r, uint32_t a) {
    asm volatile("ld.shared.v2.b32 {%0,%1}, [%2];" : "=r"(r[0]), "=r"(r[1]) : "r"(a));
}
__device__ __forceinline__ float2 lds64f(uint32_t a) {
    float2 v;
    asm volatile("ld.shared.v2.f32 {%0,%1}, [%2];" : "=f"(v.x), "=f"(v.y) : "r"(a));
    return v;
}

// pack two f32 into f16x2 (round-to-nearest)
__device__ __forceinline__ uint32_t pack2h(float a, float b) {
    __half2 h2 = __floats2half2_rn(a, b);
    return *reinterpret_cast<uint32_t*>(&h2);
}

// f32 MUFU tanh (value paths: g gate, tanh(c))
__device__ __forceinline__ float tanha(float x) {
    float y; asm("tanh.approx.f32 %0, %1;" : "=f"(y) : "f"(x)); return y;
}
// dual-state fp16 sigmoid (multiplier gates only)
__device__ __forceinline__ __half2 tanh2h(__half2 v) {
    uint32_t y, xx = *reinterpret_cast<uint32_t*>(&v);
    asm("tanh.approx.f16x2 %0, %1;" : "=r"(y) : "r"(xx));
    return *reinterpret_cast<__half2*>(&y);
}
__device__ __forceinline__ float2 sigm2(float a, float b) {
    const __half2 h5 = __float2half2_rn(0.5f);
    __half2 s = __hfma2(tanh2h(__floats2half2_rn(0.5f * a, 0.5f * b)), h5, h5);
    return __half22float2(s);
}

// m16n8k16 fp16 MMA, D += A*B (C aliased to D), f32 accumulate
__device__ __forceinline__ void mma16816(float* d, const uint32_t* a, const uint32_t* b) {
    asm volatile(
        "mma.sync.aligned.m16n8k16.row.col.f32.f16.f16.f32 "
        "{%0,%1,%2,%3}, {%4,%5,%6,%7}, {%8,%9}, {%0,%1,%2,%3};"
        : "+f"(d[0]), "+f"(d[1]), "+f"(d[2]), "+f"(d[3])
        : "r"(a[0]), "r"(a[1]), "r"(a[2]), "r"(a[3]), "r"(b[0]), "r"(b[1]));
}

// weight element with K mapping: k 0..27 -> W_ih, 28..31 -> 0, 32..95 -> W_hh
__device__ __forceinline__ float wval(const float* __restrict__ Wih,
                                      const float* __restrict__ Whh, int g, int k) {
    if (k < INP)  return Wih[g * INP + k];
    if (k < 32)   return 0.0f;
    return Whh[g * H + (k - 32)];
}

__global__ void __launch_bounds__(NT, 1) lstm_mma_kernel(
    const float* __restrict__ x,    const float* __restrict__ W_ih,
    const float* __restrict__ W_hh, const float* __restrict__ b_ih,
    const float* __restrict__ b_hh, const float* __restrict__ W_fc,
    const float* __restrict__ b_fc, float* __restrict__ out)
{
    extern __shared__ char sm[];
    const uint32_t sb  = smem_u32(sm);
    const int tid  = threadIdx.x;
    const int wid  = tid >> 5;          // warp 0..7: owns rows wid*16..wid*16+15
    const int lane = tid & 31;
    const int g8   = lane >> 2;
    const int tig  = lane & 3;
    const int b0   = blockIdx.x * MROWS;
    const int row0 = wid * 16;

    // ---- build B fragments (fp16): cols g = 8*nf + colInFrag, all 256 gates ----
    for (int ii = tid; ii < 6 * 32 * 32 * 2; ii += NT) {
        int reg = ii & 1;
        int t_  = (ii >> 1) & 31;
        int nf  = (ii >> 6) & 31;
        int kf  = ii >> 11;             // 0..5
        int k0  = kf * 16 + reg * 8 + 2 * (t_ & 3);
        int g   = 8 * nf + (t_ >> 2);
        float v0 = wval(W_ih, W_hh, g, k0);
        float v1 = wval(W_ih, W_hh, g, k0 + 1);
        uint32_t boff = (uint32_t)(((kf * 32 + nf) * 256) + t_ * 8 + reg * 4);
        sts32(sb + OFF_B + boff, pack2h(v0, v1));
    }
    // ---- bias into smem (f32) ----
    for (int g = tid; g < 256; g += NT)
        sts32(sb + OFF_BIAS + 4 * g, __float_as_uint(b_ih[g] + b_hh[g]));
    __syncthreads();    // the ONLY pre-loop barrier; loop itself is barrier-free

    // per-thread recurrent state, fully register-resident
    float c[32];
#pragma unroll
    for (int i = 0; i < 32; i++) c[i] = 0.0f;
    uint32_t a_h[4][4];                 // h as next-step A fragments (fp16), h0 = 0
#pragma unroll
    for (int i = 0; i < 4; i++)
#pragma unroll
        for (int j = 0; j < 4; j++) a_h[i][j] = 0u;

    // x row base offsets (elements) for this thread's two rows
    const int xb0 = (b0 + row0 + g8) * T * INP;
    const int xb1 = (b0 + row0 + g8 + 8) * T * INP;

    // =========================== timestep loop (no barriers) ==================
    for (int t = 0; t < T; t++) {
        const bool last = (t == T - 1);

        // ---- issue x(t) LDGs early; consumed after the h-part MMA ----
        float2 xv[2][2][2];             // [kf][half][rowpair]
#pragma unroll
        for (int kf = 0; kf < 2; kf++) {
#pragma unroll
            for (int half = 0; half < 2; half++) {
                int k0 = kf * 16 + half * 8 + 2 * tig;
                if (kf == 1 && half == 1 && tig >= 2) {   // k in 28..31 -> pad 0
                    xv[kf][half][0] = make_float2(0.f, 0.f);
                    xv[kf][half][1] = make_float2(0.f, 0.f);
                } else {
                    xv[kf][half][0] = *reinterpret_cast<const float2*>(x + xb0 + t * INP + k0);
                    xv[kf][half][1] = *reinterpret_cast<const float2*>(x + xb1 + t * INP + k0);
                }
            }
        }

        // ---- D init = bias ----
        float d[32][4];
#pragma unroll
        for (int nf = 0; nf < 32; nf++) {
            float2 b2 = lds64f(sb + OFF_BIAS + (uint32_t)(8 * nf + 2 * tig) * 4);
            d[nf][0] = b2.x; d[nf][1] = b2.y;
            d[nf][2] = b2.x; d[nf][3] = b2.y;
        }

        // ---- h-part MMA: kf 2..5, a_h register fragments (x LDGs in flight) ----
#pragma unroll
        for (int i = 0; i < 4; i++) {
#pragma unroll
            for (int nf = 0; nf < 32; nf++) {
                uint32_t bb[2];
                lds64(bb, sb + OFF_B + (uint32_t)((((i + 2) * 32 + nf) * 256) + lane * 8));
                mma16816(d[nf], a_h[i], bb);
            }
        }

        // ---- convert arrived x into A fragments ----
        uint32_t a_x[2][4];
#pragma unroll
        for (int kf = 0; kf < 2; kf++)
#pragma unroll
            for (int half = 0; half < 2; half++)
#pragma unroll
                for (int rp = 0; rp < 2; rp++)
                    a_x[kf][rp + 2 * half] = pack2h(xv[kf][half][rp].x, xv[kf][half][rp].y);

        // ---- x-part MMA: kf 0..1 ----
#pragma unroll
        for (int i = 0; i < 2; i++) {
#pragma unroll
            for (int nf = 0; nf < 32; nf++) {
                uint32_t bb[2];
                lds64(bb, sb + OFF_B + (uint32_t)(((i * 32 + nf) * 256) + lane * 8));
                mma16816(d[nf], a_x[i], bb);
            }
        }

        // ---- eltwise: gates in registers; h -> next A fragment directly ----
#pragma unroll
        for (int i = 0; i < 4; i++) {
#pragma unroll
            for (int half = 0; half < 2; half++) {
                const int nfo = 2 * i + half;
#pragma unroll
                for (int rp = 0; rp < 2; rp++) {
                    const int s0 = 2 * rp;
                    const int ci = ((i * 2 + half) * 2 + rp) * 2;
                    float2 gi = sigm2(d[nfo][s0],      d[nfo][s0 + 1]);       // gate i
                    float2 gf = sigm2(d[8 + nfo][s0],  d[8 + nfo][s0 + 1]);   // gate f
                    float2 go = sigm2(d[24 + nfo][s0], d[24 + nfo][s0 + 1]);  // gate o
                    float gg0 = tanha(d[16 + nfo][s0]);                       // gate g
                    float gg1 = tanha(d[16 + nfo][s0 + 1]);
                    float cm0 = fmaf(gf.x, c[ci],     gi.x * gg0);
                    float cm1 = fmaf(gf.y, c[ci + 1], gi.y * gg1);
                    c[ci] = cm0; c[ci + 1] = cm1;
                    float hv0 = go.x * tanha(cm0);
                    float hv1 = go.y * tanha(cm1);
                    if (!last) {
                        a_h[i][rp + 2 * half] = pack2h(hv0, hv1);
                    } else {
                        int r  = row0 + g8 + 8 * rp;
                        int u0 = 16 * i + 8 * half + 2 * tig;
                        float* hf = reinterpret_cast<float*>(sm + OFF_HF);
                        hf[r * H + u0]     = hv0;
                        hf[r * H + u0 + 1] = hv1;
                    }
                }
            }
        }
    }

    // ======================= FC epilogue (fp32 SIMT, 2-way K split) ==========
    __syncthreads();   // h_last complete
    float* smf = reinterpret_cast<float*>(sm);
    const float* hf = reinterpret_cast<const float*>(sm + OFF_HF);
    for (int i = tid; i < OUTD * H; i += NT) smf[OFF_WFC / 4 + i] = W_fc[i];
    if (tid < OUTD) smf[OFF_BFC / 4 + tid] = b_fc[tid];
    __syncthreads();
    {
        const int half = tid >> 7, rr = tid & 127;  // half sums k in [half*32, +32)
        float acc[OUTD];
#pragma unroll
        for (int o = 0; o < OUTD; o++) acc[o] = 0.0f;
#pragma unroll
        for (int p = 0; p < 32; p++) {
            int k = half * 32 + p;
            float hvv = hf[rr * H + k];
#pragma unroll
            for (int o = 0; o < OUTD; o++)
                acc[o] = fmaf(hvv, smf[OFF_WFC / 4 + o * H + k], acc[o]);
        }
#pragma unroll
        for (int o = 0; o < OUTD; o++)
            smf[OFF_PART / 4 + (half * 128 + rr) * OUTD + o] = acc[o];
    }
    __syncthreads();
    for (int i = tid; i < MROWS * OUTD; i += NT) {
        int rr = i / OUTD, o = i - rr * OUTD;
        out[(size_t)(b0 + rr) * OUTD + o] =
            smf[OFF_PART / 4 + rr * OUTD + o]
          + smf[OFF_PART / 4 + (128 + rr) * OUTD + o]
          + smf[OFF_BFC / 4 + o];
    }
}

extern "C" void kernel_launch(void* const* d_in, const int* in_sizes, int n_in,
                              void* d_out, int out_size) {
    const float* x    = (const float*)d_in[0];
    const float* W_ih = (const float*)d_in[1];
    const float* W_hh = (const float*)d_in[2];
    const float* b_ih = (const float*)d_in[3];
    const float* b_hh = (const float*)d_in[4];
    const float* W_fc = (const float*)d_in[5];
    const float* b_fc = (const float*)d_in[6];

    cudaFuncSetAttribute(lstm_mma_kernel,
                         cudaFuncAttributeMaxDynamicSharedMemorySize, SMEM_BYTES);
    lstm_mma_kernel<<<BTOT / MROWS, NT, SMEM_BYTES>>>(
        x, W_ih, W_hh, b_ih, b_hh, W_fc, b_fc, (float*)d_out);
}